// round 5
// baseline (speedup 1.0000x reference)
#include <cuda_runtime.h>
#include <cstdint>
#include <cstdio>

// Bidirectional GRU encoder: B=64, T=512, E=512, U=1024, gates (z,r,h), reset_after=True.
// out = [B,T,2U] outputs (fwd|bwd) followed by [B,2U] final state.
//
// Inner-loop design (per k): j-pair vectorized f32x2 FMAs, activations pre-duplicated
// in memory so the hot loop is pure {LDS.128, FFMA2} with zero MOV/dup instructions.

#define TT   512   // seq len
#define BB   64    // batch
#define EE   512   // embedding dim
#define UU   1024  // units
#define KC   64    // K-chunk
#define NB   128   // total blocks in persistent kernel (64 per direction)
#define NTHR 256   // threads per block (2 warps per SMSP)

typedef unsigned long long ull;

// ---------------- device scratch (static only — no cudaMalloc allowed) ----------------
__device__ float g_Xt2[(size_t)TT * EE * 2 * BB];   // [t][e][128]: x duplicated pairs, 128 MB
__device__ float g_Ht2[2][2][UU * 2 * BB];          // [dir][parity][u][128]: h duplicated, 4 MB
__device__ __align__(16) ull g_maskB[TT];           // bit b of g_maskB[t] = (enc[b][t] != 0)
__device__ unsigned g_count;                        // global barrier counter

// ---------------- helpers ----------------
__device__ __forceinline__ ull fma2(ull a, ull b, ull c) {
    ull d;
    asm("fma.rn.f32x2 %0, %1, %2, %3;" : "=l"(d) : "l"(a), "l"(b), "l"(c));
    return d;
}
__device__ __forceinline__ float lo32(ull v) { return __uint_as_float((unsigned)v); }
__device__ __forceinline__ float hi32(ull v) { return __uint_as_float((unsigned)(v >> 32)); }

__device__ __forceinline__ void cp16(void* s, const void* g) {
    unsigned sa = (unsigned)__cvta_generic_to_shared(s);
    // .cg: bypass L1. REQUIRED for g_Ht2 (cross-SM producer/consumer; L1 not coherent).
    asm volatile("cp.async.cg.shared.global [%0], [%1], 16;" :: "r"(sa), "l"(g));
}
__device__ __forceinline__ void cp_commit() { asm volatile("cp.async.commit_group;" ::: "memory"); }
__device__ __forceinline__ void cp_wait1()  { asm volatile("cp.async.wait_group 1;" ::: "memory"); }
__device__ __forceinline__ void cp_wait0()  { asm volatile("cp.async.wait_group 0;" ::: "memory"); }

// ---------------- prep: Xt2[t][e][2b] = Xt2[t][e][2b+1] = emb[enc[b][t]][e] ----------
__global__ void prep_kernel(const int* __restrict__ enc, const float* __restrict__ emb) {
    int t = blockIdx.x;
    __shared__ int tok[BB];
    if (threadIdx.x < BB) tok[threadIdx.x] = enc[threadIdx.x * TT + t];
    __syncthreads();
    for (int i = threadIdx.x; i < BB * (EE / 4); i += blockDim.x) {
        int e4 = i >> 6;
        int b  = i & 63;
        float4 v = *(const float4*)(emb + (size_t)tok[b] * EE + e4 * 4);
        size_t base = ((size_t)t * EE + (size_t)e4 * 4) * (2 * BB) + 2 * b;
        *(float2*)(g_Xt2 + base)            = make_float2(v.x, v.x);
        *(float2*)(g_Xt2 + base + 2*BB)     = make_float2(v.y, v.y);
        *(float2*)(g_Xt2 + base + 4*BB)     = make_float2(v.z, v.z);
        *(float2*)(g_Xt2 + base + 6*BB)     = make_float2(v.w, v.w);
    }
}

// ---------------- mask: pack enc!=0 into one uint64 per t ----------------
__global__ void mask_kernel(const int* __restrict__ enc) {
    int t = blockIdx.x * blockDim.x + threadIdx.x;
    if (t < TT) {
        ull m = 0;
        for (int b = 0; b < BB; b++)
            m |= (ull)(enc[b * TT + t] != 0) << b;
        g_maskB[t] = m;
    }
}

// ---------------- init: h0 -> g_Ht2[dir][0] duplicated; reset barrier ----------------
__global__ void init_kernel(const float* __restrict__ h0f, const float* __restrict__ h0b) {
    int i = blockIdx.x * blockDim.x + threadIdx.x;  // 0 .. 131071
    if (i == 0) g_count = 0u;
    int d = i >> 16;
    int r = i & 65535;
    int u = r >> 6;
    int b = r & 63;
    const float* h0 = d ? h0b : h0f;
    float v = h0[b * UU + u];
    *(float2*)&g_Ht2[d][0][u * (2 * BB) + 2 * b] = make_float2(v, v);
}

// ---------------- GEMM building blocks ----------------
// a-chunk: [KC][128] duplicated floats, contiguous 32 KB
__device__ __forceinline__ void load_a(float* dst, const float* src) {
#pragma unroll
    for (int i = 0; i < 8; i++) {
        int idx = i * NTHR + threadIdx.x;  // float4 index, 2048 total
        cp16(dst + idx * 4, src + idx * 4);
    }
    cp_commit();
}

// w-chunk: 16 j-cols (8 pairs) x 3 gates x KC k's.
// SMEM: wzr[k][jp] = float4 {z_j, z_j1, r_j, r_j1};  wh[k>>1][jp] = float4 {h pair k0, h pair k1}
__device__ __forceinline__ void ldg_w(const float* __restrict__ W, int k0, int j0, float2* v) {
#pragma unroll
    for (int i = 0; i < 6; i++) {
        int idx  = i * NTHR + threadIdx.x;   // 0..1535 pair slots
        int k    = idx / 24;
        int rem  = idx - k * 24;
        int gate = rem >> 3;
        int jp   = rem & 7;
        v[i] = *(const float2*)(W + (size_t)(k0 + k) * 3072 + (gate << 10) + j0 + 2 * jp);
    }
}
__device__ __forceinline__ void sts_w(float* wzr, float* wh, const float2* v) {
    float2* z2 = (float2*)wzr;
    float2* h2 = (float2*)wh;
#pragma unroll
    for (int i = 0; i < 6; i++) {
        int idx  = i * NTHR + threadIdx.x;
        int k    = idx / 24;
        int rem  = idx - k * 24;
        int gate = rem >> 3;
        int jp   = rem & 7;
        if (gate < 2) z2[k * 16 + jp * 2 + gate]           = v[i];
        else          h2[(k >> 1) * 16 + jp * 2 + (k & 1)] = v[i];
    }
}

// per-chunk compute: thread = (jp = j-pair, bg = 2 batch rows). Pure LDS.128 + FFMA2.
__device__ __forceinline__ void compute_chunk(const float* as, const float* wzr, const float* wh,
                                              int jp, int bg,
                                              ull* az, ull* ar, ull* ah) {
    const ulonglong2* zrp = (const ulonglong2*)wzr + jp;   // [k][8]
    const ulonglong2* hp  = (const ulonglong2*)wh  + jp;   // [k/2][8]
    const ulonglong2* ap  = (const ulonglong2*)as  + bg;   // [k][32]
#pragma unroll 4
    for (int k2 = 0; k2 < KC / 2; k2++) {
        ulonglong2 hw = hp[k2 * 8];                        // h pairs for k0, k1
        {
            ulonglong2 zr = zrp[(2 * k2) * 8];
            ulonglong2 a  = ap[(2 * k2) * 32];             // a.x = dup(b0), a.y = dup(b1)
            az[0] = fma2(zr.x, a.x, az[0]);  az[1] = fma2(zr.x, a.y, az[1]);
            ar[0] = fma2(zr.y, a.x, ar[0]);  ar[1] = fma2(zr.y, a.y, ar[1]);
            ah[0] = fma2(hw.x, a.x, ah[0]);  ah[1] = fma2(hw.x, a.y, ah[1]);
        }
        {
            ulonglong2 zr = zrp[(2 * k2 + 1) * 8];
            ulonglong2 a  = ap[(2 * k2 + 1) * 32];
            az[0] = fma2(zr.x, a.x, az[0]);  az[1] = fma2(zr.x, a.y, az[1]);
            ar[0] = fma2(zr.y, a.x, ar[0]);  ar[1] = fma2(zr.y, a.y, ar[1]);
            ah[0] = fma2(hw.y, a.x, ah[0]);  ah[1] = fma2(hw.y, a.y, ah[1]);
        }
    }
}

// double-buffered chunked GEMM accumulation over nch chunks of KC
__device__ __forceinline__ void gemm_phase(const float* abase, const float* __restrict__ W,
                                           int j0, int nch,
                                           float* as0, float* as1,
                                           float* wzr0, float* wh0, float* wzr1, float* wh1,
                                           int jp, int bg, ull* az, ull* ar, ull* ah) {
    float2 v[6];
    ldg_w(W, 0, j0, v);
    sts_w(wzr0, wh0, v);
    load_a(as0, abase);
    for (int c = 0; c < nch; c++) {
        float* ac  = (c & 1) ? as1  : as0;
        float* wzc = (c & 1) ? wzr1 : wzr0;
        float* whc = (c & 1) ? wh1  : wh0;
        if (c + 1 < nch) {
            float* an = (c & 1) ? as0 : as1;
            load_a(an, abase + (size_t)(c + 1) * KC * (2 * BB));
            ldg_w(W, (c + 1) * KC, j0, v);
            cp_wait1();
        } else {
            cp_wait0();
        }
        __syncthreads();
        compute_chunk(ac, wzc, whc, jp, bg, az, ar, ah);
        if (c + 1 < nch) {
            float* wzn = (c & 1) ? wzr0 : wzr1;
            float* whn = (c & 1) ? wh0  : wh1;
            sts_w(wzn, whn, v);
        }
        __syncthreads();
    }
}

// ---------------- persistent recurrent kernel ----------------
__global__ void __launch_bounds__(NTHR, 1)
gru_kernel(const float* __restrict__ Wx_f, const float* __restrict__ Wh_f, const float* __restrict__ b_f,
           const float* __restrict__ Wx_b, const float* __restrict__ Wh_b, const float* __restrict__ b_b,
           float* __restrict__ out) {
    extern __shared__ char smem_raw[];
    float* as0  = (float*)smem_raw;            // [KC][128]  32 KB
    float* as1  = as0  + KC * 2 * BB;          //            32 KB
    float* wzr0 = as1  + KC * 2 * BB;          // [KC][8]f4   8 KB
    float* wh0  = wzr0 + KC * 32;              // [KC/2][8]f4 4 KB
    float* wzr1 = wh0  + (KC / 2) * 32;        //             8 KB
    float* wh1  = wzr1 + KC * 32;              //             4 KB
    ull*  maskS = (ull*)(wh1 + (KC / 2) * 32); // [TT]        4 KB

    const int bid = blockIdx.x, tid = threadIdx.x;
    const int d   = bid >> 6;              // direction
    const int p   = bid & 63;              // block within direction
    const int j0  = p << 4;                // 16 j-columns per block
    const int w   = tid >> 5;              // warp 0..7
    const int ln  = tid & 31;
    const int jp  = ln & 7;                // j-pair within block
    const int bgl = ln >> 3;               // 0..3
    const int bg  = w * 4 + bgl;           // 0..31 -> batch rows 2bg, 2bg+1
    const int j   = j0 + 2 * jp;
    const int b0  = 2 * bg;

    // stage the mask bitmap into smem (one-time; 4 KB = 256 threads x 16B)
    if (tid < 256) cp16(maskS + tid * 2, g_maskB + tid * 2);
    cp_commit();

    const float* Wx   = d ? Wx_b : Wx_f;
    const float* Wh   = d ? Wh_b : Wh_f;
    const float* bias = d ? b_b  : b_f;
    float bz[2], br[2], bx[2], bh[2];
#pragma unroll
    for (int jj = 0; jj < 2; jj++) {
        bz[jj] = bias[j + jj]        + bias[3072 + j + jj];
        br[jj] = bias[1024 + j + jj] + bias[4096 + j + jj];
        bx[jj] = bias[2048 + j + jj];
        bh[jj] = bias[5120 + j + jj];
    }

    // hreg[jj][bb], oreg[jj][bb]
    float hreg[2][2], oreg[2][2];
#pragma unroll
    for (int jj = 0; jj < 2; jj++)
#pragma unroll
        for (int bb = 0; bb < 2; bb++) {
            hreg[jj][bb] = g_Ht2[d][0][(j + jj) * (2 * BB) + 2 * (b0 + bb)];
            oreg[jj][bb] = 0.f;
        }

    ull az[2], ar[2], axh[2], ahh[2];
#pragma unroll
    for (int i = 0; i < 2; i++) { az[i] = 0; ar[i] = 0; axh[i] = 0; ahh[i] = 0; }

    // x-part of step 0 (accumulates az, ar, axh)
    {
        int t0 = d ? (TT - 1) : 0;
        gemm_phase(g_Xt2 + (size_t)t0 * EE * (2 * BB), Wx, j0, EE / KC,
                   as0, as1, wzr0, wh0, wzr1, wh1, jp, bg, az, ar, axh);
    }

    for (int s = 0;; s++) {
        const int t   = d ? (TT - 1 - s) : s;
        const int par = s & 1;

        // recurrent part: hg += h @ Wh
        gemm_phase(g_Ht2[d][par], Wh, j0, UU / KC,
                   as0, as1, wzr0, wh0, wzr1, wh1, jp, bg, az, ar, ahh);

        // epilogue: gates, masking, writes
        float* hdst = g_Ht2[d][par ^ 1];
        const ull mv = maskS[t];
        const size_t ocol = (size_t)t * 2048 + (size_t)d * UU + j;
        float hv[2][2];
#pragma unroll
        for (int bb = 0; bb < 2; bb++) {
            const int b = b0 + bb;
            const bool m = (mv >> b) & 1ull;
            float zs[2] = { lo32(az[bb]),  hi32(az[bb])  };
            float rs[2] = { lo32(ar[bb]),  hi32(ar[bb])  };
            float xs[2] = { lo32(axh[bb]), hi32(axh[bb]) };
            float hs[2] = { lo32(ahh[bb]), hi32(ahh[bb]) };
#pragma unroll
            for (int jj = 0; jj < 2; jj++) {
                float ez = __expf(-(zs[jj] + bz[jj]));
                float z  = __fdividef(1.f, 1.f + ez);
                float er = __expf(-(rs[jj] + br[jj]));
                float r  = __fdividef(1.f, 1.f + er);
                float hc = tanhf(xs[jj] + bx[jj] + r * (hs[jj] + bh[jj]));
                float hn = z * hreg[jj][bb] + (1.f - z) * hc;
                hn = m ? hn : hreg[jj][bb];
                float o = m ? hn : oreg[jj][bb];
                hreg[jj][bb] = hn;
                oreg[jj][bb] = o;
                hv[jj][bb] = hn;
            }
        }
        // publish h duplicated: one STG.128 per j-row {h(b0),h(b0),h(b1),h(b1)}
#pragma unroll
        for (int jj = 0; jj < 2; jj++)
            *(float4*)&hdst[(j + jj) * (2 * BB) + 2 * b0] =
                make_float4(hv[jj][0], hv[jj][0], hv[jj][1], hv[jj][1]);
        // outputs: STG.64 per batch row (j, j+1 consecutive)
#pragma unroll
        for (int bb = 0; bb < 2; bb++)
            *(float2*)&out[(size_t)(b0 + bb) * (TT * 2048) + ocol] =
                make_float2(oreg[0][bb], oreg[1][bb]);

        if (s == TT - 1) break;

        // arrive: h(s+1) published
        __syncthreads();
        if (tid == 0) { __threadfence(); atomicAdd(&g_count, 1u); }

        // hide barrier latency: x-part of step s+1 (independent of h)
#pragma unroll
        for (int i = 0; i < 2; i++) { az[i] = 0; ar[i] = 0; axh[i] = 0; ahh[i] = 0; }
        {
            int tn = d ? (TT - 2 - s) : (s + 1);
            gemm_phase(g_Xt2 + (size_t)tn * EE * (2 * BB), Wx, j0, EE / KC,
                       as0, as1, wzr0, wh0, wzr1, wh1, jp, bg, az, ar, axh);
        }

        // wait: everyone published h(s+1)
        if (tid == 0) {
            unsigned tgt = (unsigned)(s + 1) * NB;
            volatile unsigned* pc = &g_count;
            while (*pc < tgt) { __nanosleep(32); }
            __threadfence();
        }
        __syncthreads();
    }

    // final state: [B, 2U] after the output block
    const size_t STATE_OFF = (size_t)BB * TT * 2048;
#pragma unroll
    for (int bb = 0; bb < 2; bb++)
        *(float2*)&out[STATE_OFF + (size_t)(b0 + bb) * 2048 + (size_t)d * UU + j] =
            make_float2(hreg[0][bb], hreg[1][bb]);
}

// ---------------- launcher ----------------
extern "C" void kernel_launch(void* const* d_in, const int* in_sizes, int n_in,
                              void* d_out, int out_size) {
    (void)in_sizes; (void)n_in; (void)out_size;
    const int*   enc = (const int*)  d_in[0];
    const float* h0f = (const float*)d_in[1];
    const float* h0b = (const float*)d_in[2];
    const float* emb = (const float*)d_in[3];
    const float* Wxf = (const float*)d_in[4];
    const float* Whf = (const float*)d_in[5];
    const float* bf  = (const float*)d_in[6];
    const float* Wxb = (const float*)d_in[7];
    const float* Whb = (const float*)d_in[8];
    const float* bb  = (const float*)d_in[9];
    float* out = (float*)d_out;

    // 116 KB dynamic smem: only ~92 KB used, padded so at most ONE block fits per SM
    // -> all 128 persistent blocks land on distinct SMs (barrier-safe, no SM sharing).
    const int SMEM_BYTES = 116 * 1024;
    cudaFuncSetAttribute(gru_kernel, cudaFuncAttributeMaxDynamicSharedMemorySize, SMEM_BYTES);

    prep_kernel<<<TT, 256>>>(enc, emb);
    mask_kernel<<<2, 256>>>(enc);
    init_kernel<<<512, 256>>>(h0f, h0b);
    gru_kernel<<<NB, NTHR, SMEM_BYTES>>>(Wxf, Whf, bf, Wxb, Whb, bb, out);
}

// round 6
// speedup vs baseline: 1.0348x; 1.0348x over previous
#include <cuda_runtime.h>
#include <cstdint>
#include <cstdio>

// Bidirectional GRU encoder: B=64, T=512, E=512, U=1024, gates (z,r,h), reset_after=True.
// out = [B,T,2U] outputs (fwd|bwd) followed by [B,2U] final state.
//
// v6: batch-pair is the f32x2 lane dim (a = natural float2 from smem, no dup in memory),
// weights duplicated at STS time (free), split-K across 2 warp-groups (512 threads,
// 4 warps/SMSP) with one smem reduction per step. Inner loop: 4 LDS + 6 FFMA2, zero MOV.

#define TT   512   // seq len
#define BB   64    // batch
#define EE   512   // embedding dim
#define UU   1024  // units
#define KC   64    // K-chunk
#define NB   128   // total blocks in persistent kernel (64 per direction)
#define NTHR 512   // threads per block (4 warps per SMSP, 2 split-K groups)

typedef unsigned long long ull;

// ---------------- device scratch (static only — no cudaMalloc allowed) ----------------
__device__ __align__(16) float g_Xt[(size_t)TT * EE * BB];   // [t][e][64], 64 MB
__device__ __align__(16) float g_Ht[2][2][UU * BB];          // [dir][parity][u][64], 1 MB
__device__ __align__(16) ull   g_maskB[TT];                  // bit b = (enc[b][t] != 0)
__device__ unsigned g_count;                                 // global barrier counter

// ---------------- helpers ----------------
__device__ __forceinline__ ull fma2(ull a, ull b, ull c) {
    ull d;
    asm("fma.rn.f32x2 %0, %1, %2, %3;" : "=l"(d) : "l"(a), "l"(b), "l"(c));
    return d;
}
__device__ __forceinline__ float lo32(ull v) { return __uint_as_float((unsigned)v); }
__device__ __forceinline__ float hi32(ull v) { return __uint_as_float((unsigned)(v >> 32)); }

__device__ __forceinline__ void cp16(void* s, const void* g) {
    unsigned sa = (unsigned)__cvta_generic_to_shared(s);
    // .cg: bypass L1. REQUIRED for g_Ht (cross-SM producer/consumer; L1 not coherent).
    asm volatile("cp.async.cg.shared.global [%0], [%1], 16;" :: "r"(sa), "l"(g));
}
__device__ __forceinline__ void cp_commit() { asm volatile("cp.async.commit_group;" ::: "memory"); }
__device__ __forceinline__ void cp_wait1()  { asm volatile("cp.async.wait_group 1;" ::: "memory"); }
__device__ __forceinline__ void cp_wait0()  { asm volatile("cp.async.wait_group 0;" ::: "memory"); }

// ---------------- prep: Xt[t][e][b] = emb[enc[b][t]][e] ----------------
__global__ void prep_kernel(const int* __restrict__ enc, const float* __restrict__ emb) {
    int t = blockIdx.x;
    __shared__ int tok[BB];
    if (threadIdx.x < BB) tok[threadIdx.x] = enc[threadIdx.x * TT + t];
    __syncthreads();
    for (int i = threadIdx.x; i < BB * (EE / 4); i += blockDim.x) {
        int e4 = i >> 6;
        int b  = i & 63;
        float4 v = *(const float4*)(emb + (size_t)tok[b] * EE + e4 * 4);
        size_t base = ((size_t)t * EE + (size_t)e4 * 4) * BB + b;
        g_Xt[base]          = v.x;
        g_Xt[base + BB]     = v.y;
        g_Xt[base + 2 * BB] = v.z;
        g_Xt[base + 3 * BB] = v.w;
    }
}

// ---------------- mask: pack enc!=0 into one uint64 per t ----------------
__global__ void mask_kernel(const int* __restrict__ enc) {
    int t = blockIdx.x * blockDim.x + threadIdx.x;
    if (t < TT) {
        ull m = 0;
        for (int b = 0; b < BB; b++)
            m |= (ull)(enc[b * TT + t] != 0) << b;
        g_maskB[t] = m;
    }
}

// ---------------- init: h0 -> g_Ht[dir][0]; reset barrier ----------------
__global__ void init_kernel(const float* __restrict__ h0f, const float* __restrict__ h0b) {
    int i = blockIdx.x * blockDim.x + threadIdx.x;  // 0 .. 131071
    if (i == 0) g_count = 0u;
    int d = i >> 16;
    int r = i & 65535;
    int u = r >> 6;
    int b = r & 63;
    const float* h0 = d ? h0b : h0f;
    g_Ht[d][0][u * BB + b] = h0[b * UU + u];
}

// ---------------- GEMM building blocks ----------------
// a-chunk: [KC][64] floats, 16 KB contiguous
__device__ __forceinline__ void load_a(float* dst, const float* src) {
#pragma unroll
    for (int i = 0; i < 2; i++) {
        int idx = i * NTHR + threadIdx.x;  // float4 index, 1024 total
        cp16(dst + idx * 4, src + idx * 4);
    }
    cp_commit();
}

// w-chunk: 48 cols (3 gates x 16 j) x KC k's, stored DUPLICATED:
// ws[k][jp] = 48 bytes {dup(z_j),dup(z_j1), dup(r_j),dup(r_j1), dup(h_j),dup(h_j1)}
__device__ __forceinline__ void ldg_w(const float* __restrict__ W, int k0, int j0, float* v) {
#pragma unroll
    for (int i = 0; i < 6; i++) {
        int idx  = i * NTHR + threadIdx.x;   // 0..3071
        int k    = idx / 48, c = idx - k * 48;
        int gate = c >> 4;
        int q    = c & 15;
        v[i] = W[(size_t)(k0 + k) * 3072 + (gate << 10) + j0 + q];
    }
}
__device__ __forceinline__ void sts_w(float* ws, const float* v) {
    float2* w2 = (float2*)ws;
#pragma unroll
    for (int i = 0; i < 6; i++) {
        int idx  = i * NTHR + threadIdx.x;
        int k    = idx / 48, c = idx - k * 48;
        int gate = c >> 4;
        int q    = c & 15;
        // float2 slot index: k*48 + (q>>1)*6 + gate*2 + (q&1)  -> bytes k*384 + jp*48 + gate*16 + l*8
        w2[k * 48 + (q >> 1) * 6 + gate * 2 + (q & 1)] = make_float2(v[i], v[i]);
    }
}

// per-chunk compute, split-K: group g handles k in [g*32, g*32+32).
// thread = (jp, bp): acc lanes are the batch pair (2bp, 2bp+1).
__device__ __forceinline__ void compute_chunk(const float* as, const float* ws,
                                              int g, int jp, int bp,
                                              ull* az, ull* ar, ull* ah) {
    const char* wb = (const char*)ws + jp * 48 + (size_t)g * 32 * 384;
    const ull*  ab = (const ull*)as + bp + (size_t)g * 32 * 32;
#pragma unroll 8
    for (int kk = 0; kk < KC / 2; kk++) {
        const ulonglong2* wp = (const ulonglong2*)(wb + (size_t)kk * 384);
        ulonglong2 zz = wp[0];                 // {dup(wz_j), dup(wz_j1)}
        ulonglong2 rr = wp[1];
        ulonglong2 hh = wp[2];
        ull a = ab[(size_t)kk * 32];           // {a_b0, a_b1} non-dup
        az[0] = fma2(a, zz.x, az[0]);  az[1] = fma2(a, zz.y, az[1]);
        ar[0] = fma2(a, rr.x, ar[0]);  ar[1] = fma2(a, rr.y, ar[1]);
        ah[0] = fma2(a, hh.x, ah[0]);  ah[1] = fma2(a, hh.y, ah[1]);
    }
}

// double-buffered chunked GEMM accumulation over nch chunks of KC
__device__ __forceinline__ void gemm_phase(const float* abase, const float* __restrict__ W,
                                           int j0, int nch,
                                           float* as0, float* as1, float* ws0, float* ws1,
                                           int g, int jp, int bp,
                                           ull* az, ull* ar, ull* ah) {
    float v[6];
    ldg_w(W, 0, j0, v);
    sts_w(ws0, v);
    load_a(as0, abase);
    for (int c = 0; c < nch; c++) {
        float* ac = (c & 1) ? as1 : as0;
        float* wc = (c & 1) ? ws1 : ws0;
        if (c + 1 < nch) {
            float* an = (c & 1) ? as0 : as1;
            load_a(an, abase + (size_t)(c + 1) * KC * BB);
            ldg_w(W, (c + 1) * KC, j0, v);
            cp_wait1();
        } else {
            cp_wait0();
        }
        __syncthreads();
        compute_chunk(ac, wc, g, jp, bp, az, ar, ah);
        if (c + 1 < nch) {
            float* wn = (c & 1) ? ws0 : ws1;
            sts_w(wn, v);
        }
        __syncthreads();
    }
}

// ---------------- persistent recurrent kernel ----------------
__global__ void __launch_bounds__(NTHR, 1)
gru_kernel(const float* __restrict__ Wx_f, const float* __restrict__ Wh_f, const float* __restrict__ b_f,
           const float* __restrict__ Wx_b, const float* __restrict__ Wh_b, const float* __restrict__ b_b,
           float* __restrict__ out) {
    extern __shared__ char smem_raw[];
    float* as0 = (float*)smem_raw;                 // [KC][64]     16 KB  (also reduce scratch)
    float* as1 = as0 + KC * BB;                    //              16 KB
    float* ws0 = as1 + KC * BB;                    // [KC][8][48B] 24 KB
    float* ws1 = ws0 + KC * 96;                    //              24 KB
    ull*  maskS = (ull*)(ws1 + KC * 96);           // [TT]          4 KB

    const int bid = blockIdx.x, tid = threadIdx.x;
    const int d   = bid >> 6;                // direction
    const int p   = bid & 63;                // block within direction
    const int j0  = p << 4;                  // 16 j-columns per block
    const int g   = tid >> 8;                // split-K group 0/1
    const int r   = tid & 255;
    const int w4  = r >> 5;                  // warp within group 0..7
    const int ln  = r & 31;
    const int jp  = 2 * (w4 & 3) + (ln >> 4);    // 0..7 -> j = j0+2jp, j0+2jp+1
    const int bp  = ((w4 >> 2) << 4) + (ln & 15);// 0..31 -> b = 2bp, 2bp+1
    const int j   = j0 + 2 * jp;
    const int b0  = 2 * bp;

    // stage mask bitmap (4 KB = 256 threads x 16B)
    if (tid < 256) cp16(maskS + tid * 2, g_maskB + tid * 2);
    cp_commit();

    const float* Wx   = d ? Wx_b : Wx_f;
    const float* Wh   = d ? Wh_b : Wh_f;
    const float* bias = d ? b_b  : b_f;
    float bz[2], br[2], bx[2], bh[2];
#pragma unroll
    for (int jj = 0; jj < 2; jj++) {
        bz[jj] = bias[j + jj]        + bias[3072 + j + jj];
        br[jj] = bias[1024 + j + jj] + bias[4096 + j + jj];
        bx[jj] = bias[2048 + j + jj];
        bh[jj] = bias[5120 + j + jj];
    }

    // state lives in group 0 only: hreg[jj][bb], oreg[jj][bb]
    float hreg[2][2], oreg[2][2];
#pragma unroll
    for (int jj = 0; jj < 2; jj++)
#pragma unroll
        for (int bb = 0; bb < 2; bb++) {
            hreg[jj][bb] = g_Ht[d][0][(j + jj) * BB + b0 + bb];
            oreg[jj][bb] = 0.f;
        }

    ull az[2], ar[2], axh[2], ahh[2];
#pragma unroll
    for (int i = 0; i < 2; i++) { az[i] = 0; ar[i] = 0; axh[i] = 0; ahh[i] = 0; }

    // x-part of step 0
    {
        int t0 = d ? (TT - 1) : 0;
        gemm_phase(g_Xt + (size_t)t0 * EE * BB, Wx, j0, EE / KC,
                   as0, as1, ws0, ws1, g, jp, bp, az, ar, axh);
    }

    for (int s = 0;; s++) {
        const int t   = d ? (TT - 1 - s) : s;
        const int par = s & 1;

        // recurrent part: hg += h @ Wh
        gemm_phase(g_Ht[d][par], Wh, j0, UU / KC,
                   as0, as1, ws0, ws1, g, jp, bp, az, ar, ahh);

        // ---- split-K reduce: group 1 publishes partials into as0 scratch ----
        ull* red = (ull*)as0;   // 256 threads x 8 ull = 16 KB
        if (g == 1) {
            ull* dst = red + r * 8;
            dst[0] = az[0]; dst[1] = az[1];
            dst[2] = ar[0]; dst[3] = ar[1];
            dst[4] = axh[0]; dst[5] = axh[1];
            dst[6] = ahh[0]; dst[7] = ahh[1];
        }
        __syncthreads();

        if (g == 0) {
            const ull* src = red + r * 8;
            az[0]  = fma2(src[0], 0, az[0]);  // fma2(x, 0, acc) would be x*0; use add instead
            // (replaced below with proper adds)
            ;
        }
        // proper pairwise adds (f32x2 add via two scalar adds, cheap: 8 ull -> 16 adds)
        if (g == 0) {
            const ull* src = red + r * 8;
            ull sv[8] = { src[0], src[1], src[2], src[3], src[4], src[5], src[6], src[7] };
            float* a0 = (float*)az;  float* a1 = (float*)ar;
            float* a2 = (float*)axh; float* a3 = (float*)ahh;
            const float* s0 = (const float*)&sv[0];
#pragma unroll
            for (int q = 0; q < 4; q++) { a0[q] += s0[q];      }
#pragma unroll
            for (int q = 0; q < 4; q++) { a1[q] += s0[4 + q];  }
#pragma unroll
            for (int q = 0; q < 4; q++) { a2[q] += s0[8 + q];  }
#pragma unroll
            for (int q = 0; q < 4; q++) { a3[q] += s0[12 + q]; }

            // ---- epilogue: gates, masking, writes (group 0 only) ----
            const ull mv = maskS[t];
            const size_t ocol = (size_t)t * 2048 + (size_t)d * UU + j;
            float hv[2][2];
#pragma unroll
            for (int bb = 0; bb < 2; bb++) {
                const int b = b0 + bb;
                const bool m = (mv >> b) & 1ull;
                float zs[2] = { ((float*)az)[bb],  ((float*)az)[2 + bb]  };
                float rs[2] = { ((float*)ar)[bb],  ((float*)ar)[2 + bb]  };
                float xs[2] = { ((float*)axh)[bb], ((float*)axh)[2 + bb] };
                float hs[2] = { ((float*)ahh)[bb], ((float*)ahh)[2 + bb] };
#pragma unroll
                for (int jj = 0; jj < 2; jj++) {
                    float ez = __expf(-(zs[jj] + bz[jj]));
                    float z  = __fdividef(1.f, 1.f + ez);
                    float er = __expf(-(rs[jj] + br[jj]));
                    float rg = __fdividef(1.f, 1.f + er);
                    float hc = tanhf(xs[jj] + bx[jj] + rg * (hs[jj] + bh[jj]));
                    float hn = z * hreg[jj][bb] + (1.f - z) * hc;
                    hn = m ? hn : hreg[jj][bb];
                    float o = m ? hn : oreg[jj][bb];
                    hreg[jj][bb] = hn;
                    oreg[jj][bb] = o;
                    hv[jj][bb] = hn;
                }
            }
            // publish h: one STG.64 per j-row (2 b's contiguous)
            float* hdst = g_Ht[d][par ^ 1];
#pragma unroll
            for (int jj = 0; jj < 2; jj++)
                *(float2*)&hdst[(j + jj) * BB + b0] = make_float2(hv[jj][0], hv[jj][1]);
            // outputs: STG.64 per batch row (j, j+1 consecutive)
#pragma unroll
            for (int bb = 0; bb < 2; bb++)
                *(float2*)&out[(size_t)(b0 + bb) * (TT * 2048) + ocol] =
                    make_float2(oreg[0][bb], oreg[1][bb]);
        }

        if (s == TT - 1) break;

        // arrive: h(s+1) published (sync also protects as0 scratch before x-phase reuse)
        __syncthreads();
        if (tid == 0) { __threadfence(); atomicAdd(&g_count, 1u); }

        // zero accs; hide barrier latency with x-part of step s+1 (independent of h)
#pragma unroll
        for (int i = 0; i < 2; i++) { az[i] = 0; ar[i] = 0; axh[i] = 0; ahh[i] = 0; }
        {
            int tn = d ? (TT - 2 - s) : (s + 1);
            gemm_phase(g_Xt + (size_t)tn * EE * BB, Wx, j0, EE / KC,
                       as0, as1, ws0, ws1, g, jp, bp, az, ar, axh);
        }

        // wait: everyone published h(s+1)
        if (tid == 0) {
            unsigned tgt = (unsigned)(s + 1) * NB;
            volatile unsigned* pc = &g_count;
            while (*pc < tgt) { __nanosleep(32); }
            __threadfence();
        }
        __syncthreads();
    }

    // final state: [B, 2U] after the output block (group 0 only)
    if (g == 0) {
        const size_t STATE_OFF = (size_t)BB * TT * 2048;
#pragma unroll
        for (int bb = 0; bb < 2; bb++)
            *(float2*)&out[STATE_OFF + (size_t)(b0 + bb) * 2048 + (size_t)d * UU + j] =
                make_float2(hreg[0][bb], hreg[1][bb]);
    }
}

// ---------------- launcher ----------------
extern "C" void kernel_launch(void* const* d_in, const int* in_sizes, int n_in,
                              void* d_out, int out_size) {
    (void)in_sizes; (void)n_in; (void)out_size;
    const int*   enc = (const int*)  d_in[0];
    const float* h0f = (const float*)d_in[1];
    const float* h0b = (const float*)d_in[2];
    const float* emb = (const float*)d_in[3];
    const float* Wxf = (const float*)d_in[4];
    const float* Whf = (const float*)d_in[5];
    const float* bf  = (const float*)d_in[6];
    const float* Wxb = (const float*)d_in[7];
    const float* Whb = (const float*)d_in[8];
    const float* bb  = (const float*)d_in[9];
    float* out = (float*)d_out;

    // 116 KB dynamic smem: ~84 KB used, padded so at most ONE block fits per SM
    // -> all 128 persistent blocks land on distinct SMs (barrier-safe, no SM sharing).
    const int SMEM_BYTES = 116 * 1024;
    cudaFuncSetAttribute(gru_kernel, cudaFuncAttributeMaxDynamicSharedMemorySize, SMEM_BYTES);

    prep_kernel<<<TT, 256>>>(enc, emb);
    mask_kernel<<<2, 256>>>(enc);
    init_kernel<<<512, 256>>>(h0f, h0b);
    gru_kernel<<<NB, NTHR, SMEM_BYTES>>>(Wxf, Whf, bf, Wxb, Whb, bb, out);
}

// round 7
// speedup vs baseline: 1.0362x; 1.0013x over previous
#include <cuda_runtime.h>
#include <cstdint>
#include <cstdio>

// Bidirectional GRU encoder: B=64, T=512, E=512, U=1024, gates (z,r,h), reset_after=True.
// out = [B,T,2U] outputs (fwd|bwd) followed by [B,2U] final state.
//
// v6: batch-pair is the f32x2 lane dim (a = natural float2 from smem, no dup in memory),
// weights duplicated at STS time (free), split-K across 2 warp-groups (512 threads,
// 4 warps/SMSP) with one smem reduction per step. Inner loop: 4 LDS + 6 FFMA2, zero MOV.

#define TT   512   // seq len
#define BB   64    // batch
#define EE   512   // embedding dim
#define UU   1024  // units
#define KC   64    // K-chunk
#define NB   128   // total blocks in persistent kernel (64 per direction)
#define NTHR 512   // threads per block (4 warps per SMSP, 2 split-K groups)

typedef unsigned long long ull;

// ---------------- device scratch (static only — no cudaMalloc allowed) ----------------
__device__ __align__(16) float g_Xt[(size_t)TT * EE * BB];   // [t][e][64], 64 MB
__device__ __align__(16) float g_Ht[2][2][UU * BB];          // [dir][parity][u][64], 1 MB
__device__ __align__(16) ull   g_maskB[TT];                  // bit b = (enc[b][t] != 0)
__device__ unsigned g_count;                                 // global barrier counter

// ---------------- helpers ----------------
__device__ __forceinline__ ull fma2(ull a, ull b, ull c) {
    ull d;
    asm("fma.rn.f32x2 %0, %1, %2, %3;" : "=l"(d) : "l"(a), "l"(b), "l"(c));
    return d;
}
__device__ __forceinline__ float lo32(ull v) { return __uint_as_float((unsigned)v); }
__device__ __forceinline__ float hi32(ull v) { return __uint_as_float((unsigned)(v >> 32)); }

__device__ __forceinline__ void cp16(void* s, const void* g) {
    unsigned sa = (unsigned)__cvta_generic_to_shared(s);
    // .cg: bypass L1. REQUIRED for g_Ht (cross-SM producer/consumer; L1 not coherent).
    asm volatile("cp.async.cg.shared.global [%0], [%1], 16;" :: "r"(sa), "l"(g));
}
__device__ __forceinline__ void cp_commit() { asm volatile("cp.async.commit_group;" ::: "memory"); }
__device__ __forceinline__ void cp_wait1()  { asm volatile("cp.async.wait_group 1;" ::: "memory"); }
__device__ __forceinline__ void cp_wait0()  { asm volatile("cp.async.wait_group 0;" ::: "memory"); }

// ---------------- prep: Xt[t][e][b] = emb[enc[b][t]][e] ----------------
__global__ void prep_kernel(const int* __restrict__ enc, const float* __restrict__ emb) {
    int t = blockIdx.x;
    __shared__ int tok[BB];
    if (threadIdx.x < BB) tok[threadIdx.x] = enc[threadIdx.x * TT + t];
    __syncthreads();
    for (int i = threadIdx.x; i < BB * (EE / 4); i += blockDim.x) {
        int e4 = i >> 6;
        int b  = i & 63;
        float4 v = *(const float4*)(emb + (size_t)tok[b] * EE + e4 * 4);
        size_t base = ((size_t)t * EE + (size_t)e4 * 4) * BB + b;
        g_Xt[base]          = v.x;
        g_Xt[base + BB]     = v.y;
        g_Xt[base + 2 * BB] = v.z;
        g_Xt[base + 3 * BB] = v.w;
    }
}

// ---------------- mask: pack enc!=0 into one uint64 per t ----------------
__global__ void mask_kernel(const int* __restrict__ enc) {
    int t = blockIdx.x * blockDim.x + threadIdx.x;
    if (t < TT) {
        ull m = 0;
        for (int b = 0; b < BB; b++)
            m |= (ull)(enc[b * TT + t] != 0) << b;
        g_maskB[t] = m;
    }
}

// ---------------- init: h0 -> g_Ht[dir][0]; reset barrier ----------------
__global__ void init_kernel(const float* __restrict__ h0f, const float* __restrict__ h0b) {
    int i = blockIdx.x * blockDim.x + threadIdx.x;  // 0 .. 131071
    if (i == 0) g_count = 0u;
    int d = i >> 16;
    int r = i & 65535;
    int u = r >> 6;
    int b = r & 63;
    const float* h0 = d ? h0b : h0f;
    g_Ht[d][0][u * BB + b] = h0[b * UU + u];
}

// ---------------- GEMM building blocks ----------------
// a-chunk: [KC][64] floats, 16 KB contiguous
__device__ __forceinline__ void load_a(float* dst, const float* src) {
#pragma unroll
    for (int i = 0; i < 2; i++) {
        int idx = i * NTHR + threadIdx.x;  // float4 index, 1024 total
        cp16(dst + idx * 4, src + idx * 4);
    }
    cp_commit();
}

// w-chunk: 48 cols (3 gates x 16 j) x KC k's, stored DUPLICATED:
// ws[k][jp] = 48 bytes {dup(z_j),dup(z_j1), dup(r_j),dup(r_j1), dup(h_j),dup(h_j1)}
__device__ __forceinline__ void ldg_w(const float* __restrict__ W, int k0, int j0, float* v) {
#pragma unroll
    for (int i = 0; i < 6; i++) {
        int idx  = i * NTHR + threadIdx.x;   // 0..3071
        int k    = idx / 48, c = idx - k * 48;
        int gate = c >> 4;
        int q    = c & 15;
        v[i] = W[(size_t)(k0 + k) * 3072 + (gate << 10) + j0 + q];
    }
}
__device__ __forceinline__ void sts_w(float* ws, const float* v) {
    float2* w2 = (float2*)ws;
#pragma unroll
    for (int i = 0; i < 6; i++) {
        int idx  = i * NTHR + threadIdx.x;
        int k    = idx / 48, c = idx - k * 48;
        int gate = c >> 4;
        int q    = c & 15;
        // float2 slot index: k*48 + (q>>1)*6 + gate*2 + (q&1)  -> bytes k*384 + jp*48 + gate*16 + l*8
        w2[k * 48 + (q >> 1) * 6 + gate * 2 + (q & 1)] = make_float2(v[i], v[i]);
    }
}

// per-chunk compute, split-K: group g handles k in [g*32, g*32+32).
// thread = (jp, bp): acc lanes are the batch pair (2bp, 2bp+1).
__device__ __forceinline__ void compute_chunk(const float* as, const float* ws,
                                              int g, int jp, int bp,
                                              ull* az, ull* ar, ull* ah) {
    const char* wb = (const char*)ws + jp * 48 + (size_t)g * 32 * 384;
    const ull*  ab = (const ull*)as + bp + (size_t)g * 32 * 32;
#pragma unroll 8
    for (int kk = 0; kk < KC / 2; kk++) {
        const ulonglong2* wp = (const ulonglong2*)(wb + (size_t)kk * 384);
        ulonglong2 zz = wp[0];                 // {dup(wz_j), dup(wz_j1)}
        ulonglong2 rr = wp[1];
        ulonglong2 hh = wp[2];
        ull a = ab[(size_t)kk * 32];           // {a_b0, a_b1} non-dup
        az[0] = fma2(a, zz.x, az[0]);  az[1] = fma2(a, zz.y, az[1]);
        ar[0] = fma2(a, rr.x, ar[0]);  ar[1] = fma2(a, rr.y, ar[1]);
        ah[0] = fma2(a, hh.x, ah[0]);  ah[1] = fma2(a, hh.y, ah[1]);
    }
}

// double-buffered chunked GEMM accumulation over nch chunks of KC
__device__ __forceinline__ void gemm_phase(const float* abase, const float* __restrict__ W,
                                           int j0, int nch,
                                           float* as0, float* as1, float* ws0, float* ws1,
                                           int g, int jp, int bp,
                                           ull* az, ull* ar, ull* ah) {
    float v[6];
    ldg_w(W, 0, j0, v);
    sts_w(ws0, v);
    load_a(as0, abase);
    for (int c = 0; c < nch; c++) {
        float* ac = (c & 1) ? as1 : as0;
        float* wc = (c & 1) ? ws1 : ws0;
        if (c + 1 < nch) {
            float* an = (c & 1) ? as0 : as1;
            load_a(an, abase + (size_t)(c + 1) * KC * BB);
            ldg_w(W, (c + 1) * KC, j0, v);
            cp_wait1();
        } else {
            cp_wait0();
        }
        __syncthreads();
        compute_chunk(ac, wc, g, jp, bp, az, ar, ah);
        if (c + 1 < nch) {
            float* wn = (c & 1) ? ws0 : ws1;
            sts_w(wn, v);
        }
        __syncthreads();
    }
}

// ---------------- persistent recurrent kernel ----------------
__global__ void __launch_bounds__(NTHR, 1)
gru_kernel(const float* __restrict__ Wx_f, const float* __restrict__ Wh_f, const float* __restrict__ b_f,
           const float* __restrict__ Wx_b, const float* __restrict__ Wh_b, const float* __restrict__ b_b,
           float* __restrict__ out) {
    extern __shared__ char smem_raw[];
    float* as0 = (float*)smem_raw;                 // [KC][64]     16 KB  (also reduce scratch)
    float* as1 = as0 + KC * BB;                    //              16 KB
    float* ws0 = as1 + KC * BB;                    // [KC][8][48B] 24 KB
    float* ws1 = ws0 + KC * 96;                    //              24 KB
    ull*  maskS = (ull*)(ws1 + KC * 96);           // [TT]          4 KB

    const int bid = blockIdx.x, tid = threadIdx.x;
    const int d   = bid >> 6;                // direction
    const int p   = bid & 63;                // block within direction
    const int j0  = p << 4;                  // 16 j-columns per block
    const int g   = tid >> 8;                // split-K group 0/1
    const int r   = tid & 255;
    const int w4  = r >> 5;                  // warp within group 0..7
    const int ln  = r & 31;
    const int jp  = 2 * (w4 & 3) + (ln >> 4);    // 0..7 -> j = j0+2jp, j0+2jp+1
    const int bp  = ((w4 >> 2) << 4) + (ln & 15);// 0..31 -> b = 2bp, 2bp+1
    const int j   = j0 + 2 * jp;
    const int b0  = 2 * bp;

    // stage mask bitmap (4 KB = 256 threads x 16B)
    if (tid < 256) cp16(maskS + tid * 2, g_maskB + tid * 2);
    cp_commit();

    const float* Wx   = d ? Wx_b : Wx_f;
    const float* Wh   = d ? Wh_b : Wh_f;
    const float* bias = d ? b_b  : b_f;
    float bz[2], br[2], bx[2], bh[2];
#pragma unroll
    for (int jj = 0; jj < 2; jj++) {
        bz[jj] = bias[j + jj]        + bias[3072 + j + jj];
        br[jj] = bias[1024 + j + jj] + bias[4096 + j + jj];
        bx[jj] = bias[2048 + j + jj];
        bh[jj] = bias[5120 + j + jj];
    }

    // state lives in group 0 only: hreg[jj][bb], oreg[jj][bb]
    float hreg[2][2], oreg[2][2];
#pragma unroll
    for (int jj = 0; jj < 2; jj++)
#pragma unroll
        for (int bb = 0; bb < 2; bb++) {
            hreg[jj][bb] = g_Ht[d][0][(j + jj) * BB + b0 + bb];
            oreg[jj][bb] = 0.f;
        }

    ull az[2], ar[2], axh[2], ahh[2];
#pragma unroll
    for (int i = 0; i < 2; i++) { az[i] = 0; ar[i] = 0; axh[i] = 0; ahh[i] = 0; }

    // x-part of step 0
    {
        int t0 = d ? (TT - 1) : 0;
        gemm_phase(g_Xt + (size_t)t0 * EE * BB, Wx, j0, EE / KC,
                   as0, as1, ws0, ws1, g, jp, bp, az, ar, axh);
    }

    for (int s = 0;; s++) {
        const int t   = d ? (TT - 1 - s) : s;
        const int par = s & 1;

        // recurrent part: hg += h @ Wh
        gemm_phase(g_Ht[d][par], Wh, j0, UU / KC,
                   as0, as1, ws0, ws1, g, jp, bp, az, ar, ahh);

        // ---- split-K reduce: group 1 publishes partials into as0 scratch ----
        ull* red = (ull*)as0;   // 256 threads x 8 ull = 16 KB
        if (g == 1) {
            ull* dst = red + r * 8;
            dst[0] = az[0]; dst[1] = az[1];
            dst[2] = ar[0]; dst[3] = ar[1];
            dst[4] = axh[0]; dst[5] = axh[1];
            dst[6] = ahh[0]; dst[7] = ahh[1];
        }
        __syncthreads();

        if (g == 0) {
            const ull* src = red + r * 8;
            az[0]  = fma2(src[0], 0, az[0]);  // fma2(x, 0, acc) would be x*0; use add instead
            // (replaced below with proper adds)
            ;
        }
        // proper pairwise adds (f32x2 add via two scalar adds, cheap: 8 ull -> 16 adds)
        if (g == 0) {
            const ull* src = red + r * 8;
            ull sv[8] = { src[0], src[1], src[2], src[3], src[4], src[5], src[6], src[7] };
            float* a0 = (float*)az;  float* a1 = (float*)ar;
            float* a2 = (float*)axh; float* a3 = (float*)ahh;
            const float* s0 = (const float*)&sv[0];
#pragma unroll
            for (int q = 0; q < 4; q++) { a0[q] += s0[q];      }
#pragma unroll
            for (int q = 0; q < 4; q++) { a1[q] += s0[4 + q];  }
#pragma unroll
            for (int q = 0; q < 4; q++) { a2[q] += s0[8 + q];  }
#pragma unroll
            for (int q = 0; q < 4; q++) { a3[q] += s0[12 + q]; }

            // ---- epilogue: gates, masking, writes (group 0 only) ----
            const ull mv = maskS[t];
            const size_t ocol = (size_t)t * 2048 + (size_t)d * UU + j;
            float hv[2][2];
#pragma unroll
            for (int bb = 0; bb < 2; bb++) {
                const int b = b0 + bb;
                const bool m = (mv >> b) & 1ull;
                float zs[2] = { ((float*)az)[bb],  ((float*)az)[2 + bb]  };
                float rs[2] = { ((float*)ar)[bb],  ((float*)ar)[2 + bb]  };
                float xs[2] = { ((float*)axh)[bb], ((float*)axh)[2 + bb] };
                float hs[2] = { ((float*)ahh)[bb], ((float*)ahh)[2 + bb] };
#pragma unroll
                for (int jj = 0; jj < 2; jj++) {
                    float ez = __expf(-(zs[jj] + bz[jj]));
                    float z  = __fdividef(1.f, 1.f + ez);
                    float er = __expf(-(rs[jj] + br[jj]));
                    float rg = __fdividef(1.f, 1.f + er);
                    float hc = tanhf(xs[jj] + bx[jj] + rg * (hs[jj] + bh[jj]));
                    float hn = z * hreg[jj][bb] + (1.f - z) * hc;
                    hn = m ? hn : hreg[jj][bb];
                    float o = m ? hn : oreg[jj][bb];
                    hreg[jj][bb] = hn;
                    oreg[jj][bb] = o;
                    hv[jj][bb] = hn;
                }
            }
            // publish h: one STG.64 per j-row (2 b's contiguous)
            float* hdst = g_Ht[d][par ^ 1];
#pragma unroll
            for (int jj = 0; jj < 2; jj++)
                *(float2*)&hdst[(j + jj) * BB + b0] = make_float2(hv[jj][0], hv[jj][1]);
            // outputs: STG.64 per batch row (j, j+1 consecutive)
#pragma unroll
            for (int bb = 0; bb < 2; bb++)
                *(float2*)&out[(size_t)(b0 + bb) * (TT * 2048) + ocol] =
                    make_float2(oreg[0][bb], oreg[1][bb]);
        }

        if (s == TT - 1) break;

        // arrive: h(s+1) published (sync also protects as0 scratch before x-phase reuse)
        __syncthreads();
        if (tid == 0) { __threadfence(); atomicAdd(&g_count, 1u); }

        // zero accs; hide barrier latency with x-part of step s+1 (independent of h)
#pragma unroll
        for (int i = 0; i < 2; i++) { az[i] = 0; ar[i] = 0; axh[i] = 0; ahh[i] = 0; }
        {
            int tn = d ? (TT - 2 - s) : (s + 1);
            gemm_phase(g_Xt + (size_t)tn * EE * BB, Wx, j0, EE / KC,
                       as0, as1, ws0, ws1, g, jp, bp, az, ar, axh);
        }

        // wait: everyone published h(s+1)
        if (tid == 0) {
            unsigned tgt = (unsigned)(s + 1) * NB;
            volatile unsigned* pc = &g_count;
            while (*pc < tgt) { __nanosleep(32); }
            __threadfence();
        }
        __syncthreads();
    }

    // final state: [B, 2U] after the output block (group 0 only)
    if (g == 0) {
        const size_t STATE_OFF = (size_t)BB * TT * 2048;
#pragma unroll
        for (int bb = 0; bb < 2; bb++)
            *(float2*)&out[STATE_OFF + (size_t)(b0 + bb) * 2048 + (size_t)d * UU + j] =
                make_float2(hreg[0][bb], hreg[1][bb]);
    }
}

// ---------------- launcher ----------------
extern "C" void kernel_launch(void* const* d_in, const int* in_sizes, int n_in,
                              void* d_out, int out_size) {
    (void)in_sizes; (void)n_in; (void)out_size;
    const int*   enc = (const int*)  d_in[0];
    const float* h0f = (const float*)d_in[1];
    const float* h0b = (const float*)d_in[2];
    const float* emb = (const float*)d_in[3];
    const float* Wxf = (const float*)d_in[4];
    const float* Whf = (const float*)d_in[5];
    const float* bf  = (const float*)d_in[6];
    const float* Wxb = (const float*)d_in[7];
    const float* Whb = (const float*)d_in[8];
    const float* bb  = (const float*)d_in[9];
    float* out = (float*)d_out;

    // 116 KB dynamic smem: ~84 KB used, padded so at most ONE block fits per SM
    // -> all 128 persistent blocks land on distinct SMs (barrier-safe, no SM sharing).
    const int SMEM_BYTES = 116 * 1024;
    cudaFuncSetAttribute(gru_kernel, cudaFuncAttributeMaxDynamicSharedMemorySize, SMEM_BYTES);

    prep_kernel<<<TT, 256>>>(enc, emb);
    mask_kernel<<<2, 256>>>(enc);
    init_kernel<<<512, 256>>>(h0f, h0b);
    gru_kernel<<<NB, NTHR, SMEM_BYTES>>>(Wxf, Whf, bf, Wxb, Whb, bb, out);
}

// round 8
// speedup vs baseline: 1.3627x; 1.3151x over previous
#include <cuda_runtime.h>
#include <cstdint>
#include <cstdio>

// Bidirectional GRU encoder: B=64, T=512, E=512, U=1024, gates (z,r,h), reset_after=True.
// out = [B,T,2U] outputs (fwd|bwd) followed by [B,2U] final state.
//
// v8: thread tile 2j x 4b (12 FFMA2/k), warp = 4jp x 8bq so the a-read is one
// 128B-contiguous LDS.128 wavefront and weight reads are single-wavefront broadcasts.
// Split-K x2 (8 warps, 256 thr), weights duplicated at STS time. ~16 wf/k < 24 FMA cyc/k.

#define TT   512   // seq len
#define BB   64    // batch
#define EE   512   // embedding dim
#define UU   1024  // units
#define KC   64    // K-chunk
#define NB   128   // total blocks in persistent kernel (64 per direction)
#define NTHR 256   // threads per block (2 warps per SMSP, 2 split-K groups)

typedef unsigned long long ull;

// ---------------- device scratch (static only — no cudaMalloc allowed) ----------------
__device__ __align__(16) float g_Xt[(size_t)TT * EE * BB];   // [t][e][64], 64 MB
__device__ __align__(16) float g_Ht[2][2][UU * BB];          // [dir][parity][u][64], 1 MB
__device__ __align__(16) ull   g_maskB[TT];                  // bit b = (enc[b][t] != 0)
__device__ unsigned g_count;                                 // global barrier counter

// ---------------- helpers ----------------
__device__ __forceinline__ ull fma2(ull a, ull b, ull c) {
    ull d;
    asm("fma.rn.f32x2 %0, %1, %2, %3;" : "=l"(d) : "l"(a), "l"(b), "l"(c));
    return d;
}
__device__ __forceinline__ ull add2(ull a, ull b) {
    ull d;
    asm("add.rn.f32x2 %0, %1, %2;" : "=l"(d) : "l"(a), "l"(b));
    return d;
}
__device__ __forceinline__ float lo32(ull v) { return __uint_as_float((unsigned)v); }
__device__ __forceinline__ float hi32(ull v) { return __uint_as_float((unsigned)(v >> 32)); }

__device__ __forceinline__ void cp16(void* s, const void* g) {
    unsigned sa = (unsigned)__cvta_generic_to_shared(s);
    // .cg: bypass L1. REQUIRED for g_Ht (cross-SM producer/consumer; L1 not coherent).
    asm volatile("cp.async.cg.shared.global [%0], [%1], 16;" :: "r"(sa), "l"(g));
}
__device__ __forceinline__ void cp_commit() { asm volatile("cp.async.commit_group;" ::: "memory"); }
__device__ __forceinline__ void cp_wait1()  { asm volatile("cp.async.wait_group 1;" ::: "memory"); }
__device__ __forceinline__ void cp_wait0()  { asm volatile("cp.async.wait_group 0;" ::: "memory"); }

// ---------------- prep: Xt[t][e][b] = emb[enc[b][t]][e] ----------------
__global__ void prep_kernel(const int* __restrict__ enc, const float* __restrict__ emb) {
    int t = blockIdx.x;
    __shared__ int tok[BB];
    if (threadIdx.x < BB) tok[threadIdx.x] = enc[threadIdx.x * TT + t];
    __syncthreads();
    for (int i = threadIdx.x; i < BB * (EE / 4); i += blockDim.x) {
        int e4 = i >> 6;
        int b  = i & 63;
        float4 v = *(const float4*)(emb + (size_t)tok[b] * EE + e4 * 4);
        size_t base = ((size_t)t * EE + (size_t)e4 * 4) * BB + b;
        g_Xt[base]          = v.x;
        g_Xt[base + BB]     = v.y;
        g_Xt[base + 2 * BB] = v.z;
        g_Xt[base + 3 * BB] = v.w;
    }
}

// ---------------- mask: pack enc!=0 into one uint64 per t ----------------
__global__ void mask_kernel(const int* __restrict__ enc) {
    int t = blockIdx.x * blockDim.x + threadIdx.x;
    if (t < TT) {
        ull m = 0;
        for (int b = 0; b < BB; b++)
            m |= (ull)(enc[b * TT + t] != 0) << b;
        g_maskB[t] = m;
    }
}

// ---------------- init: h0 -> g_Ht[dir][0]; reset barrier ----------------
__global__ void init_kernel(const float* __restrict__ h0f, const float* __restrict__ h0b) {
    int i = blockIdx.x * blockDim.x + threadIdx.x;  // 0 .. 131071
    if (i == 0) g_count = 0u;
    int d = i >> 16;
    int r = i & 65535;
    int u = r >> 6;
    int b = r & 63;
    const float* h0 = d ? h0b : h0f;
    g_Ht[d][0][u * BB + b] = h0[b * UU + u];
}

// ---------------- GEMM building blocks ----------------
// a-chunk: [KC][64] floats, 16 KB contiguous
__device__ __forceinline__ void load_a(float* dst, const float* src) {
#pragma unroll
    for (int i = 0; i < 4; i++) {
        int idx = i * NTHR + threadIdx.x;  // float4 index, 1024 total
        cp16(dst + idx * 4, src + idx * 4);
    }
    cp_commit();
}

// w-chunk, stored DUPLICATED per j-pair:
// ws byte offset (k, q=jpair, gate) = k*384 + q*48 + gate*16, content {w_j,w_j,w_j1,w_j1}
__device__ __forceinline__ void ldg_w(const float* __restrict__ W, int k0, int j0, float2* v) {
#pragma unroll
    for (int i = 0; i < 6; i++) {
        int idx  = i * NTHR + threadIdx.x;   // 0..1535 float2 slots
        int k    = idx / 24, rem = idx - k * 24;
        int gate = rem >> 3;
        int q    = rem & 7;
        v[i] = *(const float2*)(W + (size_t)(k0 + k) * 3072 + (gate << 10) + j0 + 2 * q);
    }
}
__device__ __forceinline__ void sts_w(float* ws, const float2* v) {
    float4* w4p = (float4*)ws;
#pragma unroll
    for (int i = 0; i < 6; i++) {
        int idx  = i * NTHR + threadIdx.x;
        int k    = idx / 24, rem = idx - k * 24;
        int gate = rem >> 3;
        int q    = rem & 7;
        w4p[k * 24 + q * 3 + gate] = make_float4(v[i].x, v[i].x, v[i].y, v[i].y);
    }
}

// per-chunk compute, split-K: group g handles k in [g*32, g*32+32).
// thread = (jp, bq): 2 j-cols (jp) x 4 batch rows (4bq..4bq+3).
// acc index [jj*2 + bu]: lanes = (b, b+1) with b = 4bq + 2bu.
__device__ __forceinline__ void compute_chunk(const float* as, const float* ws,
                                              int g, int jp, int bq,
                                              ull* az, ull* ar, ull* ah) {
    const char* wb = (const char*)ws + jp * 48 + (size_t)g * 32 * 384;
    const char* ab = (const char*)as + bq * 16 + (size_t)g * 32 * 256;
#pragma unroll 8
    for (int k = 0; k < 32; k++) {
        ulonglong2 wz = *(const ulonglong2*)(wb + (size_t)k * 384);        // {dup wz_j, dup wz_j1}
        ulonglong2 wr = *(const ulonglong2*)(wb + (size_t)k * 384 + 16);
        ulonglong2 wh = *(const ulonglong2*)(wb + (size_t)k * 384 + 32);
        ulonglong2 a  = *(const ulonglong2*)(ab + (size_t)k * 256);        // {b0b1, b2b3}
        az[0] = fma2(a.x, wz.x, az[0]);  az[1] = fma2(a.y, wz.x, az[1]);
        az[2] = fma2(a.x, wz.y, az[2]);  az[3] = fma2(a.y, wz.y, az[3]);
        ar[0] = fma2(a.x, wr.x, ar[0]);  ar[1] = fma2(a.y, wr.x, ar[1]);
        ar[2] = fma2(a.x, wr.y, ar[2]);  ar[3] = fma2(a.y, wr.y, ar[3]);
        ah[0] = fma2(a.x, wh.x, ah[0]);  ah[1] = fma2(a.y, wh.x, ah[1]);
        ah[2] = fma2(a.x, wh.y, ah[2]);  ah[3] = fma2(a.y, wh.y, ah[3]);
    }
}

// double-buffered chunked GEMM accumulation over nch chunks of KC
__device__ __forceinline__ void gemm_phase(const float* abase, const float* __restrict__ W,
                                           int j0, int nch,
                                           float* as0, float* as1, float* ws0, float* ws1,
                                           int g, int jp, int bq,
                                           ull* az, ull* ar, ull* ah) {
    float2 v[6];
    ldg_w(W, 0, j0, v);
    sts_w(ws0, v);
    load_a(as0, abase);
    for (int c = 0; c < nch; c++) {
        float* ac = (c & 1) ? as1 : as0;
        float* wc = (c & 1) ? ws1 : ws0;
        if (c + 1 < nch) {
            float* an = (c & 1) ? as0 : as1;
            load_a(an, abase + (size_t)(c + 1) * KC * BB);
            ldg_w(W, (c + 1) * KC, j0, v);
            cp_wait1();
        } else {
            cp_wait0();
        }
        __syncthreads();
        compute_chunk(ac, wc, g, jp, bq, az, ar, ah);
        if (c + 1 < nch) {
            float* wn = (c & 1) ? ws0 : ws1;
            sts_w(wn, v);
        }
        __syncthreads();
    }
}

// ---------------- persistent recurrent kernel ----------------
__global__ void __launch_bounds__(NTHR, 1)
gru_kernel(const float* __restrict__ Wx_f, const float* __restrict__ Wh_f, const float* __restrict__ b_f,
           const float* __restrict__ Wx_b, const float* __restrict__ Wh_b, const float* __restrict__ b_b,
           float* __restrict__ out) {
    extern __shared__ char smem_raw[];
    float* as0 = (float*)smem_raw;                 // [KC][64]       16 KB (also reduce scratch)
    float* as1 = as0 + KC * BB;                    //                16 KB
    float* ws0 = as1 + KC * BB;                    // [KC][8][48B]   24 KB
    float* ws1 = ws0 + KC * 96;                    //                24 KB
    ull*  maskS = (ull*)(ws1 + KC * 96);           // [TT]            4 KB

    const int bid = blockIdx.x, tid = threadIdx.x;
    const int d   = bid >> 6;                 // direction
    const int p   = bid & 63;                 // block within direction
    const int j0  = p << 4;                   // 16 j-columns per block
    const int g   = tid >> 7;                 // split-K group 0/1
    const int r   = tid & 127;
    const int w4  = r >> 5;                   // warp within group 0..3
    const int ln  = r & 31;
    const int jp  = (w4 & 1) * 4 + (ln >> 3); // 0..7 -> j = j0+2jp, +1
    const int bq  = (w4 >> 1) * 8 + (ln & 7); // 0..15 -> b = 4bq .. 4bq+3
    const int j   = j0 + 2 * jp;
    const int b0  = 4 * bq;

    // stage mask bitmap (4 KB = 256 threads x 16B)
    cp16(maskS + tid * 2, g_maskB + tid * 2);
    cp_commit();

    const float* Wx   = d ? Wx_b : Wx_f;
    const float* Wh   = d ? Wh_b : Wh_f;
    const float* bias = d ? b_b  : b_f;
    float bz[2], br[2], bx[2], bh[2];
#pragma unroll
    for (int jj = 0; jj < 2; jj++) {
        bz[jj] = bias[j + jj]        + bias[3072 + j + jj];
        br[jj] = bias[1024 + j + jj] + bias[4096 + j + jj];
        bx[jj] = bias[2048 + j + jj];
        bh[jj] = bias[5120 + j + jj];
    }

    // state lives in group 0 only: hreg[jj][bb], oreg[jj][bb], bb in 0..3
    float hreg[2][4], oreg[2][4];
#pragma unroll
    for (int jj = 0; jj < 2; jj++)
#pragma unroll
        for (int bb = 0; bb < 4; bb++) {
            hreg[jj][bb] = g_Ht[d][0][(j + jj) * BB + b0 + bb];
            oreg[jj][bb] = 0.f;
        }

    // accumulators: az/ar/axh/ahh, each [jj*2 + bu]
    ull az[4], ar[4], axh[4], ahh[4];
#pragma unroll
    for (int i = 0; i < 4; i++) { az[i] = 0; ar[i] = 0; axh[i] = 0; ahh[i] = 0; }

    // x-part of step 0
    {
        int t0 = d ? (TT - 1) : 0;
        gemm_phase(g_Xt + (size_t)t0 * EE * BB, Wx, j0, EE / KC,
                   as0, as1, ws0, ws1, g, jp, bq, az, ar, axh);
    }

    for (int s = 0;; s++) {
        const int t   = d ? (TT - 1 - s) : s;
        const int par = s & 1;

        // recurrent part: hg += h @ Wh
        gemm_phase(g_Ht[d][par], Wh, j0, UU / KC,
                   as0, as1, ws0, ws1, g, jp, bq, az, ar, ahh);

        // ---- split-K reduce (scratch = as0; last chunk used as1, so as0 is free) ----
        ull* red = (ull*)as0;   // 128 threads x 16 ull = 16 KB
        if (g == 1) {
            ulonglong2* dst = (ulonglong2*)(red + r * 16);
            dst[0] = make_ulonglong2(az[0], az[1]);
            dst[1] = make_ulonglong2(az[2], az[3]);
            dst[2] = make_ulonglong2(ar[0], ar[1]);
            dst[3] = make_ulonglong2(ar[2], ar[3]);
            dst[4] = make_ulonglong2(axh[0], axh[1]);
            dst[5] = make_ulonglong2(axh[2], axh[3]);
            dst[6] = make_ulonglong2(ahh[0], ahh[1]);
            dst[7] = make_ulonglong2(ahh[2], ahh[3]);
        }
        __syncthreads();

        if (g == 0) {
            const ull* src = red + r * 16;
#pragma unroll
            for (int q = 0; q < 4; q++) {
                az[q]  = add2(az[q],  src[q]);
                ar[q]  = add2(ar[q],  src[4 + q]);
                axh[q] = add2(axh[q], src[8 + q]);
                ahh[q] = add2(ahh[q], src[12 + q]);
            }

            // ---- epilogue: gates, masking, writes (group 0 only) ----
            const ull mv = maskS[t];
            const size_t ocol = (size_t)t * 2048 + (size_t)d * UU + j;
            float hv[2][4];
#pragma unroll
            for (int bb = 0; bb < 4; bb++) {
                const int bu = bb >> 1, lidx = bb & 1;
                const bool m = (mv >> (b0 + bb)) & 1ull;
#pragma unroll
                for (int jj = 0; jj < 2; jj++) {
                    const int ai = jj * 2 + bu;
                    float zs = lidx ? hi32(az[ai])  : lo32(az[ai]);
                    float rs = lidx ? hi32(ar[ai])  : lo32(ar[ai]);
                    float xs = lidx ? hi32(axh[ai]) : lo32(axh[ai]);
                    float hs = lidx ? hi32(ahh[ai]) : lo32(ahh[ai]);
                    float ez = __expf(-(zs + bz[jj]));
                    float z  = __fdividef(1.f, 1.f + ez);
                    float er = __expf(-(rs + br[jj]));
                    float rg = __fdividef(1.f, 1.f + er);
                    float hc = tanhf(xs + bx[jj] + rg * (hs + bh[jj]));
                    float hn = z * hreg[jj][bb] + (1.f - z) * hc;
                    hn = m ? hn : hreg[jj][bb];
                    float o = m ? hn : oreg[jj][bb];
                    hreg[jj][bb] = hn;
                    oreg[jj][bb] = o;
                    hv[jj][bb] = hn;
                }
            }
            // publish h: one STG.128 per j-row (4 b's contiguous)
            float* hdst = g_Ht[d][par ^ 1];
#pragma unroll
            for (int jj = 0; jj < 2; jj++)
                *(float4*)&hdst[(j + jj) * BB + b0] =
                    make_float4(hv[jj][0], hv[jj][1], hv[jj][2], hv[jj][3]);
            // outputs: STG.64 per batch row (j, j+1 consecutive)
#pragma unroll
            for (int bb = 0; bb < 4; bb++)
                *(float2*)&out[(size_t)(b0 + bb) * (TT * 2048) + ocol] =
                    make_float2(oreg[0][bb], oreg[1][bb]);
        }

        if (s == TT - 1) break;

        // arrive: h(s+1) published (sync also protects as0 scratch before reuse)
        __syncthreads();
        if (tid == 0) { __threadfence(); atomicAdd(&g_count, 1u); }

        // zero accs; hide barrier latency with x-part of step s+1 (independent of h)
#pragma unroll
        for (int i = 0; i < 4; i++) { az[i] = 0; ar[i] = 0; axh[i] = 0; ahh[i] = 0; }
        {
            int tn = d ? (TT - 2 - s) : (s + 1);
            gemm_phase(g_Xt + (size_t)tn * EE * BB, Wx, j0, EE / KC,
                       as0, as1, ws0, ws1, g, jp, bq, az, ar, axh);
        }

        // wait: everyone published h(s+1)
        if (tid == 0) {
            unsigned tgt = (unsigned)(s + 1) * NB;
            volatile unsigned* pc = &g_count;
            while (*pc < tgt) { __nanosleep(32); }
            __threadfence();
        }
        __syncthreads();
    }

    // final state: [B, 2U] after the output block (group 0 only)
    if (g == 0) {
        const size_t STATE_OFF = (size_t)BB * TT * 2048;
#pragma unroll
        for (int bb = 0; bb < 4; bb++)
            *(float2*)&out[STATE_OFF + (size_t)(b0 + bb) * 2048 + (size_t)d * UU + j] =
                make_float2(hreg[0][bb], hreg[1][bb]);
    }
}

// ---------------- launcher ----------------
extern "C" void kernel_launch(void* const* d_in, const int* in_sizes, int n_in,
                              void* d_out, int out_size) {
    (void)in_sizes; (void)n_in; (void)out_size;
    const int*   enc = (const int*)  d_in[0];
    const float* h0f = (const float*)d_in[1];
    const float* h0b = (const float*)d_in[2];
    const float* emb = (const float*)d_in[3];
    const float* Wxf = (const float*)d_in[4];
    const float* Whf = (const float*)d_in[5];
    const float* bf  = (const float*)d_in[6];
    const float* Wxb = (const float*)d_in[7];
    const float* Whb = (const float*)d_in[8];
    const float* bb  = (const float*)d_in[9];
    float* out = (float*)d_out;

    // 116 KB dynamic smem: ~84 KB used, padded so at most ONE block fits per SM
    // -> all 128 persistent blocks land on distinct SMs (barrier-safe, no SM sharing).
    const int SMEM_BYTES = 116 * 1024;
    cudaFuncSetAttribute(gru_kernel, cudaFuncAttributeMaxDynamicSharedMemorySize, SMEM_BYTES);

    prep_kernel<<<TT, 256>>>(enc, emb);
    mask_kernel<<<2, 256>>>(enc);
    init_kernel<<<512, 256>>>(h0f, h0b);
    gru_kernel<<<NB, NTHR, SMEM_BYTES>>>(Wxf, Whf, bf, Wxb, Whb, bb, out);
}